// round 8
// baseline (speedup 1.0000x reference)
#include <cuda_runtime.h>

#define TLEN 4096
#define BROWS 2048
#define SHIFTW 10
#define NSHIFT 21
#define THREADS 256
#define QUADS_PER_THREAD (TLEN / (THREADS * 4))
#define HALO 12

__device__ float g_row_mse[BROWS];
__device__ unsigned int g_done = 0;

__global__ __launch_bounds__(THREADS, 6) void shift_loss_kernel(
    const float* __restrict__ x, const float* __restrict__ y,
    float* __restrict__ out)
{
    const int row = blockIdx.x;
    const float* __restrict__ xr = x + (size_t)row * TLEN;
    const float* __restrict__ yr = y + (size_t)row * TLEN;
    const int tid = threadIdx.x;
    const int lane = tid & 31;
    const int wid = tid >> 5;

    __shared__ float ys[HALO + TLEN + HALO + 4];   // zero-padded y row
    __shared__ float red[THREADS / 32][25];
    __shared__ float tot[25];
    __shared__ float corr_sh[NSHIFT];
    __shared__ float mse_sh[NSHIFT];
    __shared__ int is_last_sh;

    // ---- stage y row into smem with zero halos; fold sy/syy into staging ----
    if (tid < HALO) {
        ys[tid] = 0.f;
        ys[HALO + TLEN + tid] = 0.f;
    }
    float sy = 0.f, syy = 0.f;
#pragma unroll
    for (int it = 0; it < QUADS_PER_THREAD; ++it) {
        const int t0 = (it * THREADS + tid) * 4;
        const float4 v = __ldcs(reinterpret_cast<const float4*>(yr + t0));
        sy  += v.x + v.y + v.z + v.w;
        syy += v.x * v.x + v.y * v.y + v.z * v.z + v.w * v.w;
        *reinterpret_cast<float4*>(&ys[HALO + t0]) = v;   // byte off 48+16k: aligned
    }
    __syncthreads();

    float acc[NSHIFT];
#pragma unroll
    for (int s = 0; s < NSHIFT; ++s) acc[s] = 0.f;
    float sx = 0.f, sxx = 0.f;

#pragma unroll
    for (int it = 0; it < QUADS_PER_THREAD; ++it) {
        const int t0 = (it * THREADS + tid) * 4;

        const float4 xv = __ldcs(reinterpret_cast<const float4*>(xr + t0));
        float xk[4] = {xv.x, xv.y, xv.z, xv.w};
#pragma unroll
        for (int k = 0; k < 4; ++k) { sx += xk[k]; sxx += xk[k] * xk[k]; }

        // window w[i] = y[t0-12+i] = ys[t0 + i] (HALO cancels the -12);
        // 7 conflict-free LDS.128, zero halo = validity mask, no predicates.
#pragma unroll
        for (int j = 0; j < 7; ++j) {
            const float4 v = *reinterpret_cast<const float4*>(&ys[t0 + 4 * j]);
            float w4[4] = {v.x, v.y, v.z, v.w};
#pragma unroll
            for (int c = 0; c < 4; ++c) {
                const int i = 4 * j + c;
#pragma unroll
                for (int k = 0; k < 4; ++k) {
                    const int s = i - k - 2;       // compile-time after unroll
                    if (s >= 0 && s < NSHIFT)
                        acc[s] += xk[k] * w4[c];
                }
            }
        }
    }

    // ---- block reduction of 25 partials ----
    float vals[25];
    vals[0] = sx; vals[1] = sxx; vals[2] = sy; vals[3] = syy;
#pragma unroll
    for (int s = 0; s < NSHIFT; ++s) vals[4 + s] = acc[s];

#pragma unroll
    for (int i = 0; i < 25; ++i) {
#pragma unroll
        for (int o = 16; o > 0; o >>= 1)
            vals[i] += __shfl_down_sync(0xffffffffu, vals[i], o);
    }
    if (lane == 0) {
#pragma unroll
        for (int i = 0; i < 25; ++i) red[wid][i] = vals[i];
    }
    __syncthreads();
    if (tid < 25) {
        float t = 0.f;
#pragma unroll
        for (int wb = 0; wb < THREADS / 32; ++wb) t += red[wb][tid];
        tot[tid] = t;
    }
    __syncthreads();

    // ---- 21 threads: per-shift trimmed Pearson + MSE ----
    if (tid < NSHIFT) {
        const int sh = tid - SHIFTW;
        float Sx = tot[0], Sxx = tot[1], Sy = tot[2], Syy = tot[3];
        const int m = sh < 0 ? -sh : sh;
        const float n = (float)(TLEN - m);
        if (sh > 0) {
            for (int i = 0; i < sh; ++i) {
                const float xv2 = xr[TLEN - 1 - i]; Sx -= xv2; Sxx -= xv2 * xv2;
                const float yv2 = ys[HALO + i];     Sy -= yv2; Syy -= yv2 * yv2;
            }
        } else if (sh < 0) {
            for (int i = 0; i < m; ++i) {
                const float xv2 = xr[i];                   Sx -= xv2; Sxx -= xv2 * xv2;
                const float yv2 = ys[HALO + TLEN - 1 - i]; Sy -= yv2; Syy -= yv2 * yv2;
            }
        }
        const float Sxy = tot[4 + tid];
        const float inv_n = 1.f / n;
        const float cov = Sxy - Sx * Sy * inv_n;
        const float vx  = Sxx - Sx * Sx * inv_n;
        const float vy  = Syy - Sy * Sy * inv_n;
        corr_sh[tid] = cov * rsqrtf(vx * vy);
        mse_sh[tid]  = (Sxx + Syy - 2.f * Sxy) * inv_n;
    }
    __syncthreads();

    if (tid == 0) {
        float best = corr_sh[0];
        int bi = 0;
#pragma unroll
        for (int s = 1; s < NSHIFT; ++s) {
            if (corr_sh[s] > best) { best = corr_sh[s]; bi = s; }  // first-max tie-break
        }
        g_row_mse[row] = mse_sh[bi];
        __threadfence();
        const unsigned int prev = atomicAdd(&g_done, 1u);
        is_last_sh = (prev == BROWS - 1u) ? 1 : 0;
    }
    __syncthreads();

    // ---- last block: fused final mean (deterministic fixed-order sum) ----
    if (is_last_sh) {
        float s = 0.f;
#pragma unroll
        for (int i = 0; i < BROWS / THREADS; ++i)
            s += __ldcg(&g_row_mse[i * THREADS + tid]);
#pragma unroll
        for (int o = 16; o > 0; o >>= 1) s += __shfl_down_sync(0xffffffffu, s, o);
        if (lane == 0) red[wid][0] = s;
        __syncthreads();
        if (tid == 0) {
            float t = 0.f;
#pragma unroll
            for (int wb = 0; wb < THREADS / 32; ++wb) t += red[wb][0];
            out[0] = t / (float)BROWS;
            g_done = 0;  // reset for next graph replay
        }
    }
}

extern "C" void kernel_launch(void* const* d_in, const int* in_sizes, int n_in,
                              void* d_out, int out_size)
{
    const float* x = (const float*)d_in[0];
    const float* y = (const float*)d_in[1];
    shift_loss_kernel<<<BROWS, THREADS>>>(x, y, (float*)d_out);
}

// round 9
// speedup vs baseline: 1.4113x; 1.4113x over previous
#include <cuda_runtime.h>

#define TLEN 4096
#define BROWS 2048
#define SHIFTW 10
#define NSHIFT 21
#define THREADS 256
#define QUADS_PER_THREAD (TLEN / (THREADS * 4))
#define HALO 12

__device__ float g_row_mse[BROWS];
__device__ unsigned int g_done = 0;

typedef unsigned long long u64_t;

// packed f32x2 FMA / ADD (Blackwell FFMA2 — only reachable via PTX)
__device__ __forceinline__ void ffma2(float2& d, const float2& a, const float2& b) {
    asm("fma.rn.f32x2 %0, %1, %2, %0;"
        : "+l"(reinterpret_cast<u64_t&>(d))
        : "l"(reinterpret_cast<const u64_t&>(a)),
          "l"(reinterpret_cast<const u64_t&>(b)));
}
__device__ __forceinline__ void fadd2(float2& d, const float2& a) {
    asm("add.rn.f32x2 %0, %1, %0;"
        : "+l"(reinterpret_cast<u64_t&>(d))
        : "l"(reinterpret_cast<const u64_t&>(a)));
}

__global__ __launch_bounds__(THREADS, 4) void shift_loss_kernel(
    const float* __restrict__ x, const float* __restrict__ y,
    float* __restrict__ out)
{
    const int row = blockIdx.x;
    const float* __restrict__ xr = x + (size_t)row * TLEN;
    const float* __restrict__ yr = y + (size_t)row * TLEN;
    const int tid = threadIdx.x;
    const int lane = tid & 31;
    const int wid = tid >> 5;

    __shared__ float ys[HALO + TLEN + HALO + 4];   // zero-padded y row
    __shared__ float red[THREADS / 32][25];
    __shared__ float tot[25];
    __shared__ float corr_sh[NSHIFT];
    __shared__ float mse_sh[NSHIFT];
    __shared__ int is_last_sh;

    // ---- stage y row into smem with zero halos; fold sy/syy into staging ----
    if (tid < HALO) {
        ys[tid] = 0.f;
        ys[HALO + TLEN + tid] = 0.f;
    }
    float sy = 0.f, syy = 0.f;
#pragma unroll
    for (int it = 0; it < QUADS_PER_THREAD; ++it) {
        const int t0 = (it * THREADS + tid) * 4;
        const float4 v = *reinterpret_cast<const float4*>(yr + t0);
        sy  += v.x + v.y + v.z + v.w;
        syy += v.x * v.x + v.y * v.y + v.z * v.z + v.w * v.w;
        *reinterpret_cast<float4*>(&ys[HALO + t0]) = v;   // byte off 48+16k: aligned
    }
    __syncthreads();

    // even shifts s=2e (e=0..10) packed as float2; odd shifts s=2o+1 (o=0..9) scalar
    float2 accE[11];
    float  accO[10];
#pragma unroll
    for (int e = 0; e < 11; ++e) accE[e] = make_float2(0.f, 0.f);
#pragma unroll
    for (int o = 0; o < 10; ++o) accO[o] = 0.f;
    float2 sx2 = make_float2(0.f, 0.f), sxx2 = make_float2(0.f, 0.f);

#pragma unroll
    for (int it = 0; it < QUADS_PER_THREAD; ++it) {
        const int t0 = (it * THREADS + tid) * 4;

        const float4 xv = *reinterpret_cast<const float4*>(xr + t0);
        const float2 X01 = make_float2(xv.x, xv.y);
        const float2 X23 = make_float2(xv.z, xv.w);
        const float  xk[4] = {xv.x, xv.y, xv.z, xv.w};
        fadd2(sx2, X01);  fadd2(sx2, X23);
        ffma2(sxx2, X01, X01);  ffma2(sxx2, X23, X23);

        // window w[i] = y[t0-12+i] = ys[t0 + i]; 7 conflict-free LDS.128,
        // zero halo = validity mask. Window quad j carries pairs E[2j], E[2j+1].
#pragma unroll
        for (int j = 0; j < 7; ++j) {
            const float4 v = *reinterpret_cast<const float4*>(&ys[t0 + 4 * j]);
            const float w4[4] = {v.x, v.y, v.z, v.w};
            const float2 P[2] = {make_float2(v.x, v.y), make_float2(v.z, v.w)};

            // even shifts: acc[2e] += X01·E[e+1] + X23·E[e+2]  (E[m]=pair m)
#pragma unroll
            for (int p = 0; p < 2; ++p) {
                const int m = 2 * j + p;
                if (m >= 1 && m <= 11) ffma2(accE[m - 1], X01, P[p]);
                if (m >= 2 && m <= 12) ffma2(accE[m - 2], X23, P[p]);
            }
            // odd shifts: scalar FFMA. w[i]=w4[c], i=4j+c feeds s=i-k-2 (odd only)
#pragma unroll
            for (int c = 0; c < 4; ++c) {
                const int i = 4 * j + c;
#pragma unroll
                for (int k = 0; k < 4; ++k) {
                    const int s = i - k - 2;       // compile-time after unroll
                    if (s >= 0 && s < NSHIFT && (s & 1))
                        accO[(s - 1) >> 1] += xk[k] * w4[c];
                }
            }
        }
    }

    // ---- block reduction of 25 partials ----
    float vals[25];
    vals[0] = sx2.x + sx2.y; vals[1] = sxx2.x + sxx2.y;
    vals[2] = sy;            vals[3] = syy;
#pragma unroll
    for (int s = 0; s < NSHIFT; ++s)
        vals[4 + s] = (s & 1) ? accO[(s - 1) >> 1]
                              : (accE[s >> 1].x + accE[s >> 1].y);

#pragma unroll
    for (int i = 0; i < 25; ++i) {
#pragma unroll
        for (int o = 16; o > 0; o >>= 1)
            vals[i] += __shfl_down_sync(0xffffffffu, vals[i], o);
    }
    if (lane == 0) {
#pragma unroll
        for (int i = 0; i < 25; ++i) red[wid][i] = vals[i];
    }
    __syncthreads();
    if (tid < 25) {
        float t = 0.f;
#pragma unroll
        for (int wb = 0; wb < THREADS / 32; ++wb) t += red[wb][tid];
        tot[tid] = t;
    }
    __syncthreads();

    // ---- 21 threads: per-shift trimmed Pearson + MSE ----
    if (tid < NSHIFT) {
        const int sh = tid - SHIFTW;
        float Sx = tot[0], Sxx = tot[1], Sy = tot[2], Syy = tot[3];
        const int m = sh < 0 ? -sh : sh;
        const float n = (float)(TLEN - m);
        if (sh > 0) {
            for (int i = 0; i < sh; ++i) {
                const float xv2 = xr[TLEN - 1 - i]; Sx -= xv2; Sxx -= xv2 * xv2;
                const float yv2 = ys[HALO + i];     Sy -= yv2; Syy -= yv2 * yv2;
            }
        } else if (sh < 0) {
            for (int i = 0; i < m; ++i) {
                const float xv2 = xr[i];                   Sx -= xv2; Sxx -= xv2 * xv2;
                const float yv2 = ys[HALO + TLEN - 1 - i]; Sy -= yv2; Syy -= yv2 * yv2;
            }
        }
        const float Sxy = tot[4 + tid];
        const float inv_n = 1.f / n;
        const float cov = Sxy - Sx * Sy * inv_n;
        const float vx  = Sxx - Sx * Sx * inv_n;
        const float vy  = Syy - Sy * Sy * inv_n;
        corr_sh[tid] = cov * rsqrtf(vx * vy);
        mse_sh[tid]  = (Sxx + Syy - 2.f * Sxy) * inv_n;
    }
    __syncthreads();

    if (tid == 0) {
        float best = corr_sh[0];
        int bi = 0;
#pragma unroll
        for (int s = 1; s < NSHIFT; ++s) {
            if (corr_sh[s] > best) { best = corr_sh[s]; bi = s; }  // first-max tie-break
        }
        g_row_mse[row] = mse_sh[bi];
        __threadfence();
        const unsigned int prev = atomicAdd(&g_done, 1u);
        is_last_sh = (prev == BROWS - 1u) ? 1 : 0;
    }
    __syncthreads();

    // ---- last block: fused final mean (deterministic fixed-order sum) ----
    if (is_last_sh) {
        float s = 0.f;
#pragma unroll
        for (int i = 0; i < BROWS / THREADS; ++i)
            s += __ldcg(&g_row_mse[i * THREADS + tid]);
#pragma unroll
        for (int o = 16; o > 0; o >>= 1) s += __shfl_down_sync(0xffffffffu, s, o);
        if (lane == 0) red[wid][0] = s;
        __syncthreads();
        if (tid == 0) {
            float t = 0.f;
#pragma unroll
            for (int wb = 0; wb < THREADS / 32; ++wb) t += red[wb][0];
            out[0] = t / (float)BROWS;
            g_done = 0;  // reset for next graph replay
        }
    }
}

extern "C" void kernel_launch(void* const* d_in, const int* in_sizes, int n_in,
                              void* d_out, int out_size)
{
    const float* x = (const float*)d_in[0];
    const float* y = (const float*)d_in[1];
    shift_loss_kernel<<<BROWS, THREADS>>>(x, y, (float*)d_out);
}

// round 10
// speedup vs baseline: 1.5313x; 1.0850x over previous
#include <cuda_runtime.h>

#define TLEN 4096
#define BROWS 2048
#define SHIFTW 10
#define NSHIFT 21
#define THREADS 256
#define QPT (TLEN / (THREADS * 4))   /* 4 quads per thread */
#define HALO 12

__device__ float g_row_mse[BROWS];
__device__ unsigned int g_done = 0;

__global__ __launch_bounds__(THREADS, 5) void shift_loss_kernel(
    const float* __restrict__ x, const float* __restrict__ y,
    float* __restrict__ out)
{
    const int row = blockIdx.x;
    const float* __restrict__ xr = x + (size_t)row * TLEN;
    const float* __restrict__ yr = y + (size_t)row * TLEN;
    const int tid = threadIdx.x;
    const int lane = tid & 31;
    const int wid = tid >> 5;

    __shared__ float ys[HALO + TLEN + HALO + 4];   // zero-padded y row
    __shared__ float red[THREADS / 32][25];
    __shared__ float tot[25];
    __shared__ float corr_sh[NSHIFT];
    __shared__ float mse_sh[NSHIFT];
    __shared__ float xe_lo[12], xe_hi[12];         // x row edges for trim
    __shared__ int is_last_sh;

    // ---- stage y row into smem with zero halos; fold sy/syy into staging ----
    if (tid < HALO) {
        ys[tid] = 0.f;
        ys[HALO + TLEN + tid] = 0.f;
    }
    float sy = 0.f, syy = 0.f;
#pragma unroll
    for (int it = 0; it < QPT; ++it) {
        const int t0 = (it * THREADS + tid) * 4;
        const float4 v = *reinterpret_cast<const float4*>(yr + t0);
        sy  += v.x + v.y + v.z + v.w;
        syy += v.x * v.x + v.y * v.y + v.z * v.z + v.w * v.w;
        *reinterpret_cast<float4*>(&ys[HALO + t0]) = v;   // byte off 48+16k: aligned
    }
    __syncthreads();

    float acc[NSHIFT];
#pragma unroll
    for (int s = 0; s < NSHIFT; ++s) acc[s] = 0.f;
    float sx = 0.f, sxx = 0.f;

#pragma unroll
    for (int it = 0; it < QPT; ++it) {
        const int t0 = (it * THREADS + tid) * 4;

        const float4 xv = *reinterpret_cast<const float4*>(xr + t0);
        float xk[4] = {xv.x, xv.y, xv.z, xv.w};
#pragma unroll
        for (int k = 0; k < 4; ++k) { sx += xk[k]; sxx += xk[k] * xk[k]; }

        // capture x edges for the trim epilogue (2 warps, predicated)
        if (it == 0 && tid < 3) {
#pragma unroll
            for (int c = 0; c < 4; ++c) xe_lo[tid * 4 + c] = xk[c];
        }
        if (it == QPT - 1 && tid >= THREADS - 3) {
#pragma unroll
            for (int c = 0; c < 4; ++c) xe_hi[(tid - (THREADS - 3)) * 4 + c] = xk[c];
        }

        // window w[i] = y[t0-12+i] = ys[t0+i]; shifts use only w[2..25]:
        // 2 LDS.64 edges + 5 LDS.128 (all aligned, conflict-free), zero halo = mask.
        float w[28];
        {
            const float2 ea = *reinterpret_cast<const float2*>(&ys[t0 + 2]);
            w[2] = ea.x; w[3] = ea.y;
#pragma unroll
            for (int j = 1; j <= 5; ++j) {
                const float4 v = *reinterpret_cast<const float4*>(&ys[t0 + 4 * j]);
                w[4 * j + 0] = v.x; w[4 * j + 1] = v.y;
                w[4 * j + 2] = v.z; w[4 * j + 3] = v.w;
            }
            const float2 eb = *reinterpret_cast<const float2*>(&ys[t0 + 24]);
            w[24] = eb.x; w[25] = eb.y;
        }

#pragma unroll
        for (int i = 2; i <= 25; ++i) {
#pragma unroll
            for (int k = 0; k < 4; ++k) {
                const int s = i - k - 2;           // compile-time after unroll
                if (s >= 0 && s < NSHIFT)
                    acc[s] += xk[k] * w[i];
            }
        }
    }

    // ---- block reduction of 25 partials ----
    float vals[25];
    vals[0] = sx; vals[1] = sxx; vals[2] = sy; vals[3] = syy;
#pragma unroll
    for (int s = 0; s < NSHIFT; ++s) vals[4 + s] = acc[s];

#pragma unroll
    for (int i = 0; i < 25; ++i) {
#pragma unroll
        for (int o = 16; o > 0; o >>= 1)
            vals[i] += __shfl_down_sync(0xffffffffu, vals[i], o);
    }
    if (lane == 0) {
#pragma unroll
        for (int i = 0; i < 25; ++i) red[wid][i] = vals[i];
    }
    __syncthreads();
    if (tid < 25) {
        float t = 0.f;
#pragma unroll
        for (int wb = 0; wb < THREADS / 32; ++wb) t += red[wb][tid];
        tot[tid] = t;
    }
    __syncthreads();

    // ---- 21 threads: per-shift trimmed Pearson + MSE (all-smem trim) ----
    if (tid < NSHIFT) {
        const int sh = tid - SHIFTW;
        float Sx = tot[0], Sxx = tot[1], Sy = tot[2], Syy = tot[3];
        const int m = sh < 0 ? -sh : sh;
        const float n = (float)(TLEN - m);
        if (sh > 0) {
            for (int i = 0; i < sh; ++i) {
                const float xv2 = xe_hi[11 - i];   // x[TLEN-1-i]
                Sx -= xv2; Sxx -= xv2 * xv2;
                const float yv2 = ys[HALO + i];    // y[i]
                Sy -= yv2; Syy -= yv2 * yv2;
            }
        } else if (sh < 0) {
            for (int i = 0; i < m; ++i) {
                const float xv2 = xe_lo[i];                // x[i]
                Sx -= xv2; Sxx -= xv2 * xv2;
                const float yv2 = ys[HALO + TLEN - 1 - i]; // y[TLEN-1-i]
                Sy -= yv2; Syy -= yv2 * yv2;
            }
        }
        const float Sxy = tot[4 + tid];
        const float inv_n = 1.f / n;
        const float cov = Sxy - Sx * Sy * inv_n;
        const float vx  = Sxx - Sx * Sx * inv_n;
        const float vy  = Syy - Sy * Sy * inv_n;
        corr_sh[tid] = cov * rsqrtf(vx * vy);
        mse_sh[tid]  = (Sxx + Syy - 2.f * Sxy) * inv_n;
    }
    __syncthreads();

    if (tid == 0) {
        float best = corr_sh[0];
        int bi = 0;
#pragma unroll
        for (int s = 1; s < NSHIFT; ++s) {
            if (corr_sh[s] > best) { best = corr_sh[s]; bi = s; }  // first-max tie-break
        }
        g_row_mse[row] = mse_sh[bi];
        __threadfence();
        const unsigned int prev = atomicAdd(&g_done, 1u);
        is_last_sh = (prev == BROWS - 1u) ? 1 : 0;
    }
    __syncthreads();

    // ---- last block: fused final mean (deterministic fixed-order sum) ----
    if (is_last_sh) {
        float s = 0.f;
#pragma unroll
        for (int i = 0; i < BROWS / THREADS; ++i)
            s += __ldcg(&g_row_mse[i * THREADS + tid]);
#pragma unroll
        for (int o = 16; o > 0; o >>= 1) s += __shfl_down_sync(0xffffffffu, s, o);
        if (lane == 0) red[wid][0] = s;
        __syncthreads();
        if (tid == 0) {
            float t = 0.f;
#pragma unroll
            for (int wb = 0; wb < THREADS / 32; ++wb) t += red[wb][0];
            out[0] = t / (float)BROWS;
            g_done = 0;  // reset for next graph replay
        }
    }
}

extern "C" void kernel_launch(void* const* d_in, const int* in_sizes, int n_in,
                              void* d_out, int out_size)
{
    const float* x = (const float*)d_in[0];
    const float* y = (const float*)d_in[1];
    shift_loss_kernel<<<BROWS, THREADS>>>(x, y, (float*)d_out);
}